// round 16
// baseline (speedup 1.0000x reference)
#include <cuda_runtime.h>
#include <math.h>
#include <stdint.h>

// NF4 quantize-dequantize, straight-through forward: out = data_type[idx]*s,
// s = per-row max|x| (clip 1e-6), idx = searchsorted(boundaries, x/s, left).
//
// R15 = R12 (winner, 104.4us) with ONE change: single-load sentinel LUT.
//  - 2052-cell table over u = x*(1024/s)+1025. Cell width s/1024 << min
//    threshold gap (~0.085*s), so only ~15 cells contain a boundary.
//  - Non-boundary cell: Ftab[k] stores the final value. Hot path per elem:
//    FFMA(magic) -> AND -> one LDS.32 -> signed-int sentinel test. No second
//    load, no select (99.3% of elements).
//  - Boundary cell: Ftab[k] = qNaN sentinel 0x7FC00000|jb. Rare path (~0.7%)
//    recomputes exactly: q = (x > Tsm[jb]) ? Vsm[jb+1] : Vsm[jb].
//  - Sentinel test: signed (int)bits >= 0x7FC00000 -- true only for the
//    sentinel (outputs are finite; negatives are signed-negative).
// Everything else identical to R12: row in registers (16/thread @ NT=512),
// 3 blocks/SM, dynamic row claiming, prefetch of claimed row right after the
// reduce, .cs streaming stores, exact threshold construction.
//
// Exactness: thresholds T_j = largest float with RN(t/s) <= b_j (nextafter-
// refined) => (x/s > b_j) == (x > T_j) bit-exact. Sentinel cells compute the
// exact compare; non-sentinel cells contain no threshold (pad only widens
// the sentinel set, which is safe).

#define COLS   8192
#define NF4    2048          // float4 per row
#define NT     512
#define CH     4             // float4 per thread per row (2048/512)
#define NB     15
#define NL     16
#define NCELL  2052          // u in [0, 2050] (+slop)
#define GRID   444           // 3 blocks/SM x 148 SMs

__device__ int g_row_counter;

__global__ void init_counter_kernel(int start) { g_row_counter = start; }

__device__ __forceinline__ void stg_cs(float4* p, float4 v) {
    asm volatile("st.global.cs.v4.f32 [%0], {%1,%2,%3,%4};"
                 :: "l"(p), "f"(v.x), "f"(v.y), "f"(v.z), "f"(v.w) : "memory");
}
__device__ __forceinline__ void prefetch_l2(const void* p) {
    asm volatile("prefetch.global.L2 [%0];" :: "l"(p));
}

__global__ __launch_bounds__(NT, 3)
void nf4_kernel(const float* __restrict__ x,
                const float* __restrict__ bnd,
                const float* __restrict__ dt,
                float* __restrict__ out,
                int rows)
{
    __shared__ float Ftab[NCELL];       // value or qNaN sentinel per cell
    __shared__ float Tsm[NB];
    __shared__ float Vsm[NL];
    __shared__ float wmax[NT / 32];
    __shared__ int rnS;

    const int tid = threadIdx.x;
    const int lane = tid & 31;
    const float4* __restrict__ xv = (const float4*)x;
    float4* __restrict__ ov = (float4*)out;
    const float MAGIC = 8388608.0f + 1025.0f;   // 2^23 + 1025
    const int SENT = 0x7FC00000;

    int r = blockIdx.x;                 // launcher guarantees grid <= rows
    if (r >= rows) return;

    while (true) {
        // ---- pass A: row -> registers, fused absmax ----
        float4 va[CH];
        float m = 0.0f;
        {
            const float4* rp = xv + (size_t)r * NF4;
#pragma unroll
            for (int i = 0; i < CH; i++) {
                va[i] = __ldg(rp + tid + i * NT);
                m = fmaxf(m, fmaxf(fmaxf(fabsf(va[i].x), fabsf(va[i].y)),
                                   fmaxf(fabsf(va[i].z), fabsf(va[i].w))));
            }
        }
#pragma unroll
        for (int o = 16; o; o >>= 1) m = fmaxf(m, __shfl_xor_sync(0xffffffffu, m, o));
        if (lane == 0) wmax[tid >> 5] = m;
        if (tid == 64) rnS = atomicAdd(&g_row_counter, 1);   // claim next row
        __syncthreads();    // also: prev iter's table readers are done
        float s;
        {
            float t0 = fmaxf(fmaxf(wmax[0], wmax[1]),  fmaxf(wmax[2], wmax[3]));
            float t1 = fmaxf(fmaxf(wmax[4], wmax[5]),  fmaxf(wmax[6], wmax[7]));
            float t2 = fmaxf(fmaxf(wmax[8], wmax[9]),  fmaxf(wmax[10], wmax[11]));
            float t3 = fmaxf(fmaxf(wmax[12], wmax[13]), fmaxf(wmax[14], wmax[15]));
            s = fmaxf(fmaxf(t0, t1), fmaxf(t2, t3));
        }
        s = fmaxf(s, 1e-6f);            // jnp.clip(..., 1e-6)
        const float c1 = __fdiv_rn(1024.0f, s);

        // ---- prefetch claimed next row (overlaps thresholds/LUT + pass B) ----
        const int rn = rnS;
        if (rn < rows) {
            const char* np = (const char*)(xv + (size_t)rn * NF4);
            prefetch_l2(np + (size_t)tid * 64);   // 512 thr x 64B = 32KB row
        }

        // ---- exact raw-x thresholds + scaled levels ----
        if (tid < NB) {
            const float mid = __ldg(bnd + tid);
            float t = mid * s;
            for (int it = 0; it < 8 && __fdiv_rn(t, s) <= mid; it++)
                t = nextafterf(t, __int_as_float(0x7f800000));
            for (int it = 0; it < 8 && __fdiv_rn(t, s) > mid; it++)
                t = nextafterf(t, __int_as_float(0xff800000));
            Tsm[tid] = t;
        }
        if (tid >= 32 && tid < 32 + NL)
            Vsm[tid - 32] = __ldg(dt + tid - 32) * s;   // RN, matches dt[idx]*s
        __syncthreads();

        // ---- build sentinel LUT over u = x*(1024/s) + 1025 ----
        {
            const float w = s * 0.0009765625f;   // s/1024
            const float padc = 0.05f * w;
#pragma unroll
            for (int k0 = 0; k0 < 5; k0++) {
                const int k = tid + k0 * NT;
                if (k < NCELL) {
                    const float L = ((float)k - 1025.5f) * w - padc;
                    const float R = ((float)k - 1024.5f) * w + padc;
                    int jb = 0;
#pragma unroll
                    for (int jj = 0; jj < NB; jj++) jb += (Tsm[jj] < L) ? 1 : 0;
                    float v;
                    if (jb < NB && Tsm[jb] <= R) {
                        v = __int_as_float(SENT | jb);   // boundary cell
                    } else {
                        v = Vsm[jb];                     // unique value
                    }
                    Ftab[k] = v;
                }
            }
        }
        __syncthreads();

        // ---- pass B: quantize from registers, streaming-store ----
        {
            float4* wp = ov + (size_t)r * NF4;
#pragma unroll
            for (int i = 0; i < CH; i++) {
                const float4 b = va[i];
                float4 q;
                {
                    const int k = __float_as_int(fmaf(b.x, c1, MAGIC)) & 0xFFF;
                    q.x = Ftab[k];
                    const int bi = __float_as_int(q.x);
                    if (bi >= SENT) {
                        const int jb = bi & 0xF;
                        q.x = (b.x > Tsm[jb]) ? Vsm[jb + 1] : Vsm[jb];
                    }
                }
                {
                    const int k = __float_as_int(fmaf(b.y, c1, MAGIC)) & 0xFFF;
                    q.y = Ftab[k];
                    const int bi = __float_as_int(q.y);
                    if (bi >= SENT) {
                        const int jb = bi & 0xF;
                        q.y = (b.y > Tsm[jb]) ? Vsm[jb + 1] : Vsm[jb];
                    }
                }
                {
                    const int k = __float_as_int(fmaf(b.z, c1, MAGIC)) & 0xFFF;
                    q.z = Ftab[k];
                    const int bi = __float_as_int(q.z);
                    if (bi >= SENT) {
                        const int jb = bi & 0xF;
                        q.z = (b.z > Tsm[jb]) ? Vsm[jb + 1] : Vsm[jb];
                    }
                }
                {
                    const int k = __float_as_int(fmaf(b.w, c1, MAGIC)) & 0xFFF;
                    q.w = Ftab[k];
                    const int bi = __float_as_int(q.w);
                    if (bi >= SENT) {
                        const int jb = bi & 0xF;
                        q.w = (b.w > Tsm[jb]) ? Vsm[jb + 1] : Vsm[jb];
                    }
                }
                stg_cs(wp + tid + i * NT, q);
            }
        }

        if (rn >= rows) break;
        r = rn;
    }
}

extern "C" void kernel_launch(void* const* d_in, const int* in_sizes, int n_in,
                              void* d_out, int out_size)
{
    const float* x = nullptr;
    const float* bnd = nullptr;
    const float* dt = nullptr;
    long long nx = 0;
    for (int i = 0; i < n_in; i++) {
        if (in_sizes[i] == NB)      bnd = (const float*)d_in[i];
        else if (in_sizes[i] == NL) dt  = (const float*)d_in[i];
        else { x = (const float*)d_in[i]; nx = in_sizes[i]; }
    }
    const int rows = (int)(nx / COLS);
    const int grid = rows < GRID ? rows : GRID;

    init_counter_kernel<<<1, 1>>>(grid);   // rows [0, grid) claimed statically
    nf4_kernel<<<grid, NT>>>(x, bnd, dt, (float*)d_out, rows);
}

// round 17
// speedup vs baseline: 1.5510x; 1.5510x over previous
#include <cuda_runtime.h>
#include <math.h>
#include <stdint.h>

// NF4 quantize-dequantize, straight-through forward: out = data_type[idx]*s,
// s = per-row max|x| (clip 1e-6), idx = searchsorted(boundaries, x/s, left).
//
// R17 = R12 (winner, 104.4us) with ONE change: the 258-cell table stores a
// sentinel-or-value instead of {T, vlo/vhi}. Build cost identical to R12
// (same single-pass 258-cell loop; R15's regression came from an 8x bigger
// table build, not from the sentinel concept).
//  - Non-boundary cell (243/258): Ftab[k] = final value. Hot path per elem:
//    FFMA(magic) -> AND -> one LDS.32 -> signed sentinel test. No dependent
//    second LDS, no address select.
//  - Boundary cell: Ftab[k] = qNaN sentinel 0x7FC00000|jb. Rare path (~6-8%
//    of elements, ~2 lanes/warp): q = (x > Tsm[jb]) ? Vsm[jb+1] : Vsm[jb]
//    from 15/16-entry near-broadcast arrays. Bit-exact.
//  - Sentinel test is signed: finite outputs have bits < 0x7F800000 (or are
//    signed-negative), so only the sentinel passes.
// Everything else identical to R12: row in registers (16/thread @ NT=512),
// 3 blocks/SM, dynamic row claiming, prefetch of the claimed row right after
// the reduce, .cs streaming stores, exact threshold construction.
//
// Exactness (proven): thresholds T_j = largest float with RN(t/s) <= b_j
// (nextafter-refined) => (x/s > b_j) == (x > T_j) bit-exact. 258-cell LUT
// over u = x*(128/s)+129 via magic-FMA; cell width s/128 << min threshold
// gap (~0.085*s) => <=1 threshold per cell; pad only widens the sentinel
// set, which is safe.

#define COLS   8192
#define NF4    2048          // float4 per row
#define NT     512
#define CH     4             // float4 per thread per row (2048/512)
#define NB     15
#define NL     16
#define NCELL  258
#define GRID   444           // 3 blocks/SM x 148 SMs

__device__ int g_row_counter;

__global__ void init_counter_kernel(int start) { g_row_counter = start; }

__device__ __forceinline__ void stg_cs(float4* p, float4 v) {
    asm volatile("st.global.cs.v4.f32 [%0], {%1,%2,%3,%4};"
                 :: "l"(p), "f"(v.x), "f"(v.y), "f"(v.z), "f"(v.w) : "memory");
}
__device__ __forceinline__ void prefetch_l2(const void* p) {
    asm volatile("prefetch.global.L2 [%0];" :: "l"(p));
}

__global__ __launch_bounds__(NT, 3)
void nf4_kernel(const float* __restrict__ x,
                const float* __restrict__ bnd,
                const float* __restrict__ dt,
                float* __restrict__ out,
                int rows)
{
    __shared__ float Ftab[NCELL];       // value or qNaN sentinel per cell
    __shared__ float Tsm[NB];
    __shared__ float Vsm[NL];
    __shared__ float wmax[NT / 32];
    __shared__ int rnS;

    const int tid = threadIdx.x;
    const int lane = tid & 31;
    const float4* __restrict__ xv = (const float4*)x;
    float4* __restrict__ ov = (float4*)out;
    const float MAGIC = 8388608.0f + 129.0f;   // 2^23 + 129
    const int SENT = 0x7FC00000;

    int r = blockIdx.x;                 // launcher guarantees grid <= rows
    if (r >= rows) return;

    while (true) {
        // ---- pass A: row -> registers, fused absmax ----
        float4 va[CH];
        float m = 0.0f;
        {
            const float4* rp = xv + (size_t)r * NF4;
#pragma unroll
            for (int i = 0; i < CH; i++) {
                va[i] = __ldg(rp + tid + i * NT);
                m = fmaxf(m, fmaxf(fmaxf(fabsf(va[i].x), fabsf(va[i].y)),
                                   fmaxf(fabsf(va[i].z), fabsf(va[i].w))));
            }
        }
#pragma unroll
        for (int o = 16; o; o >>= 1) m = fmaxf(m, __shfl_xor_sync(0xffffffffu, m, o));
        if (lane == 0) wmax[tid >> 5] = m;
        if (tid == 64) rnS = atomicAdd(&g_row_counter, 1);   // claim next row
        __syncthreads();    // also: prev iter's table readers are done
        float s;
        {
            float t0 = fmaxf(fmaxf(wmax[0], wmax[1]),  fmaxf(wmax[2], wmax[3]));
            float t1 = fmaxf(fmaxf(wmax[4], wmax[5]),  fmaxf(wmax[6], wmax[7]));
            float t2 = fmaxf(fmaxf(wmax[8], wmax[9]),  fmaxf(wmax[10], wmax[11]));
            float t3 = fmaxf(fmaxf(wmax[12], wmax[13]), fmaxf(wmax[14], wmax[15]));
            s = fmaxf(fmaxf(t0, t1), fmaxf(t2, t3));
        }
        s = fmaxf(s, 1e-6f);            // jnp.clip(..., 1e-6)
        const float c1 = __fdiv_rn(128.0f, s);

        // ---- prefetch claimed next row (overlaps thresholds/LUT + pass B) ----
        const int rn = rnS;
        if (rn < rows) {
            const char* np = (const char*)(xv + (size_t)rn * NF4);
            prefetch_l2(np + (size_t)tid * 64);   // 512 thr x 64B = 32KB row
        }

        // ---- exact raw-x thresholds + scaled levels ----
        if (tid < NB) {
            const float mid = __ldg(bnd + tid);
            float t = mid * s;
            for (int it = 0; it < 8 && __fdiv_rn(t, s) <= mid; it++)
                t = nextafterf(t, __int_as_float(0x7f800000));
            for (int it = 0; it < 8 && __fdiv_rn(t, s) > mid; it++)
                t = nextafterf(t, __int_as_float(0xff800000));
            Tsm[tid] = t;
        }
        if (tid >= 32 && tid < 32 + NL)
            Vsm[tid - 32] = __ldg(dt + tid - 32) * s;   // RN, matches dt[idx]*s
        __syncthreads();

        // ---- build 258-cell sentinel LUT (same cost as R12's build) ----
        if (tid < NCELL) {
            const float w = s * 0.0078125f;   // s/128
            const float padc = 0.05f * w;
            const float L = ((float)tid - 129.5f) * w - padc;
            const float R = ((float)tid - 128.5f) * w + padc;
            int jb = 0;
#pragma unroll
            for (int jj = 0; jj < NB; jj++) jb += (Tsm[jj] < L) ? 1 : 0;
            float v;
            if (jb < NB && Tsm[jb] <= R) {
                v = __int_as_float(SENT | jb);   // boundary cell: sentinel
            } else {
                v = Vsm[jb];                     // unique value for this cell
            }
            Ftab[tid] = v;
        }
        __syncthreads();

        // ---- pass B: quantize from registers, streaming-store ----
        {
            float4* wp = ov + (size_t)r * NF4;
#pragma unroll
            for (int i = 0; i < CH; i++) {
                const float4 b = va[i];
                float4 q;
                {
                    const int k = __float_as_int(fmaf(b.x, c1, MAGIC)) & 0x3ff;
                    q.x = Ftab[k];
                    const int bi = __float_as_int(q.x);
                    if (bi >= SENT) {
                        const int jb = bi & 0xF;
                        q.x = (b.x > Tsm[jb]) ? Vsm[jb + 1] : Vsm[jb];
                    }
                }
                {
                    const int k = __float_as_int(fmaf(b.y, c1, MAGIC)) & 0x3ff;
                    q.y = Ftab[k];
                    const int bi = __float_as_int(q.y);
                    if (bi >= SENT) {
                        const int jb = bi & 0xF;
                        q.y = (b.y > Tsm[jb]) ? Vsm[jb + 1] : Vsm[jb];
                    }
                }
                {
                    const int k = __float_as_int(fmaf(b.z, c1, MAGIC)) & 0x3ff;
                    q.z = Ftab[k];
                    const int bi = __float_as_int(q.z);
                    if (bi >= SENT) {
                        const int jb = bi & 0xF;
                        q.z = (b.z > Tsm[jb]) ? Vsm[jb + 1] : Vsm[jb];
                    }
                }
                {
                    const int k = __float_as_int(fmaf(b.w, c1, MAGIC)) & 0x3ff;
                    q.w = Ftab[k];
                    const int bi = __float_as_int(q.w);
                    if (bi >= SENT) {
                        const int jb = bi & 0xF;
                        q.w = (b.w > Tsm[jb]) ? Vsm[jb + 1] : Vsm[jb];
                    }
                }
                stg_cs(wp + tid + i * NT, q);
            }
        }

        if (rn >= rows) break;
        r = rn;
    }
}

extern "C" void kernel_launch(void* const* d_in, const int* in_sizes, int n_in,
                              void* d_out, int out_size)
{
    const float* x = nullptr;
    const float* bnd = nullptr;
    const float* dt = nullptr;
    long long nx = 0;
    for (int i = 0; i < n_in; i++) {
        if (in_sizes[i] == NB)      bnd = (const float*)d_in[i];
        else if (in_sizes[i] == NL) dt  = (const float*)d_in[i];
        else { x = (const float*)d_in[i]; nx = in_sizes[i]; }
    }
    const int rows = (int)(nx / COLS);
    const int grid = rows < GRID ? rows : GRID;

    init_counter_kernel<<<1, 1>>>(grid);   // rows [0, grid) claimed statically
    nf4_kernel<<<grid, NT>>>(x, bnd, dt, (float*)d_out, rows);
}